// round 6
// baseline (speedup 1.0000x reference)
#include <cuda_runtime.h>
#include <cstdint>

// Problem constants
#define BATCH     64
#define NPER      786432
#define VPER      (NPER / 4)              // 196608 int4 per row
#define LEVELS    256
#define HTHREADS  256
#define BPR       16                      // hist CTAs per row -> 1024 CTAs
#define V_PER_CTA (VPER / BPR)            // 12288 int4
#define ITERS     (V_PER_CTA / HTHREADS)  // 48 int4 per thread

// Statically zero; every launch returns them to zero -> graph-replay safe.
__device__ unsigned int g_hist[BATCH * LEVELS];   // per-row histograms
__device__ unsigned int g_cnt[BATCH];             // arrival tickets per row

// ---------------------------------------------------------------------------
// Single fused kernel, last-arriver broadcast (NO cross-CTA spinning ->
// no co-residency requirement -> grid can exceed one resident wave).
//
// Phase 1 (hist): lane-private smem counter copies sh[v*32+lane] (bank==lane,
//   conflict-free), red.shared increments (no return, no dependent chain),
//   reduce 32 copies, one global RED per bin into g_hist.
// Phase 2: ticket on g_cnt[b]. The LAST CTA of row b broadcasts the whole
//   row (256 bins x 256 cols) and resets g_hist row + g_cnt[b]. Others exit.
// ---------------------------------------------------------------------------
__global__ void __launch_bounds__(HTHREADS)
fused_kernel(const int4* __restrict__ x, float4* __restrict__ out) {
    __shared__ unsigned int sh[LEVELS * 32];   // 32 KB
    __shared__ unsigned int s_last;

    #pragma unroll
    for (int i = threadIdx.x; i < LEVELS * 32; i += HTHREADS) sh[i] = 0u;
    __syncthreads();

    const unsigned lane = threadIdx.x & 31u;
    unsigned int hbase = (unsigned int)__cvta_generic_to_shared(sh) + (lane << 2);

    const int b = blockIdx.y;
    const int4* __restrict__ blk =
        x + (size_t)b * VPER + (size_t)blockIdx.x * V_PER_CTA;

    #pragma unroll 4
    for (int it = 0; it < ITERS; it++) {
        int4 v = blk[it * HTHREADS + threadIdx.x];
        asm volatile("red.shared.add.u32 [%0], %1;"
                     :: "r"(hbase + ((unsigned)v.x << 7)), "r"(1u) : "memory");
        asm volatile("red.shared.add.u32 [%0], %1;"
                     :: "r"(hbase + ((unsigned)v.y << 7)), "r"(1u) : "memory");
        asm volatile("red.shared.add.u32 [%0], %1;"
                     :: "r"(hbase + ((unsigned)v.z << 7)), "r"(1u) : "memory");
        asm volatile("red.shared.add.u32 [%0], %1;"
                     :: "r"(hbase + ((unsigned)v.w << 7)), "r"(1u) : "memory");
    }
    __syncthreads();

    // Reduce the 32 lane-copies of bin t (rotated start -> conflict-free),
    // one spread-address global RED per bin.
    {
        const unsigned t = threadIdx.x;
        unsigned int s = 0;
        #pragma unroll
        for (int c = 0; c < 32; c++) s += sh[t * 32 + ((c + t) & 31u)];
        atomicAdd(&g_hist[(unsigned)b * LEVELS + t], s);
    }

    // ---- Phase 2: last-arriver election ----
    __threadfence();                 // publish this thread's REDG
    __syncthreads();                 // whole CTA published
    if (threadIdx.x == 0)
        s_last = (atomicAdd(&g_cnt[b], 1u) == BPR - 1) ? 1u : 0u;
    __syncthreads();
    if (!s_last) return;             // not last: done

    // ---- Last CTA of row b: broadcast the full row ----
    __threadfence();                 // acquire: all row-b REDGs visible

    float* shf = (float*)sh;         // reuse smem: 256 bin values as float
    {
        const unsigned t = threadIdx.x;
        shf[t] = (float)g_hist[(unsigned)b * LEVELS + t];
        g_hist[(unsigned)b * LEVELS + t] = 0u;   // reset for next replay
        if (t == 0) g_cnt[b] = 0u;
    }
    __syncthreads();

    // 256 bins x 64 float4 = 16384 float4; 64 per thread, coalesced.
    float4* __restrict__ dst = out + (size_t)b * LEVELS * (LEVELS / 4);
    #pragma unroll 4
    for (int k = threadIdx.x; k < LEVELS * (LEVELS / 4); k += HTHREADS) {
        float v = shf[k >> 6];
        dst[k] = make_float4(v, v, v, v);
    }
}

// ---------------------------------------------------------------------------
extern "C" void kernel_launch(void* const* d_in, const int* in_sizes, int n_in,
                              void* d_out, int out_size) {
    const int4* x = (const int4*)d_in[0];
    float4* out = (float4*)d_out;

    dim3 grid(BPR, BATCH);
    fused_kernel<<<grid, HTHREADS>>>(x, out);
}

// round 7
// speedup vs baseline: 1.0848x; 1.0848x over previous
#include <cuda_runtime.h>
#include <cstdint>

// Problem constants
#define BATCH     64
#define NPER      786432
#define VPER      (NPER / 4)              // 196608 int4 per row
#define LEVELS    256
#define HTHREADS  256
#define BPR       12                      // CTAs per row -> 768 CTAs total
#define V_PER_CTA (VPER / BPR)            // 16384 int4
#define ITERS     (V_PER_CTA / HTHREADS)  // 64 int4 per thread

// Statically zero; each launch restores zeros -> graph-replay deterministic.
__device__ unsigned int g_hist[BATCH * LEVELS];
__device__ unsigned int g_cnt[BATCH];     // arrival tickets
__device__ unsigned int g_flag[BATCH];    // row-complete flag
__device__ unsigned int g_done[BATCH];    // broadcast-done tickets

// ---------------------------------------------------------------------------
// Fused kernel, spin-release broadcast (round-5 structure, higher occupancy).
//
// Co-residency proof: smem 33KB -> 6 CTAs/SM (198KB<=228), threads 1536<=2048,
// launch_bounds(256,6) caps regs so 6/SM is guaranteed -> 888 resident slots
// >= 768 CTAs -> whole grid is ONE wave -> the flag spin cannot deadlock.
//
// Phase 1: lane-private smem copies sh[v*32+lane] (bank==lane, conflict-free),
//   red.shared increments; reduce 32 copies; one REDG per bin into g_hist.
// Phase 2: ticket; last CTA of row raises flag; all row CTAs spin-release.
// Phase 3: CTA i broadcasts its disjoint bin slice of row b; resets its bins;
//   last finisher (g_done ticket) resets the row's sync words.
// ---------------------------------------------------------------------------
__global__ void __launch_bounds__(HTHREADS, 6)
fused_kernel(const int4* __restrict__ x, float4* __restrict__ out) {
    __shared__ unsigned int sh[LEVELS * 32];   // 32 KB
    __shared__ unsigned int s_last;

    #pragma unroll
    for (int i = threadIdx.x; i < LEVELS * 32; i += HTHREADS) sh[i] = 0u;
    __syncthreads();

    const unsigned lane = threadIdx.x & 31u;
    unsigned int hbase = (unsigned int)__cvta_generic_to_shared(sh) + (lane << 2);

    const int b = blockIdx.y;
    const int i = blockIdx.x;
    const int4* __restrict__ blk =
        x + (size_t)b * VPER + (size_t)i * V_PER_CTA;

    #pragma unroll 4
    for (int it = 0; it < ITERS; it++) {
        int4 v = blk[it * HTHREADS + threadIdx.x];
        asm volatile("red.shared.add.u32 [%0], %1;"
                     :: "r"(hbase + ((unsigned)v.x << 7)), "r"(1u) : "memory");
        asm volatile("red.shared.add.u32 [%0], %1;"
                     :: "r"(hbase + ((unsigned)v.y << 7)), "r"(1u) : "memory");
        asm volatile("red.shared.add.u32 [%0], %1;"
                     :: "r"(hbase + ((unsigned)v.z << 7)), "r"(1u) : "memory");
        asm volatile("red.shared.add.u32 [%0], %1;"
                     :: "r"(hbase + ((unsigned)v.w << 7)), "r"(1u) : "memory");
    }
    __syncthreads();

    // Reduce the 32 lane-copies of bin t (rotated -> conflict-free), one REDG.
    {
        const unsigned t = threadIdx.x;
        unsigned int s = 0;
        #pragma unroll
        for (int c = 0; c < 32; c++) s += sh[t * 32 + ((c + t) & 31u)];
        atomicAdd(&g_hist[(unsigned)b * LEVELS + t], s);
    }

    // ---- Phase 2: row-completion spin-release ----
    __threadfence();
    __syncthreads();
    if (threadIdx.x == 0) {
        unsigned t = atomicAdd(&g_cnt[b], 1u);
        if (t == BPR - 1) atomicExch(&g_flag[b], 1u);
        while (*(volatile unsigned*)&g_flag[b] == 0u) __nanosleep(64);
    }
    __syncthreads();
    __threadfence();   // acquire: row-b g_hist complete

    // ---- Phase 3: broadcast bin slice [lo, hi) of row b ----
    const int lo = (i * LEVELS) / BPR;
    const int hi = ((i + 1) * LEVELS) / BPR;
    const int nbins = hi - lo;                  // 21 or 22

    float* shf = (float*)sh;
    if (threadIdx.x < (unsigned)nbins) {
        unsigned g = (unsigned)b * LEVELS + lo + threadIdx.x;
        shf[threadIdx.x] = (float)g_hist[g];
        g_hist[g] = 0u;                          // disjoint slice -> safe reset
    }
    __syncthreads();

    float4* __restrict__ dst =
        out + ((size_t)b * LEVELS + (size_t)lo) * (LEVELS / 4);
    const int total = nbins * (LEVELS / 4);      // <= 1408 float4
    for (int k = threadIdx.x; k < total; k += HTHREADS) {
        float v = shf[k >> 6];
        dst[k] = make_float4(v, v, v, v);
    }

    // last CTA of the row to finish resets the sync words
    if (threadIdx.x == 0) {
        __threadfence();
        unsigned d = atomicAdd(&g_done[b], 1u);
        if (d == BPR - 1) {
            g_cnt[b]  = 0u;
            g_flag[b] = 0u;
            g_done[b] = 0u;
            __threadfence();
        }
    }
}

// ---------------------------------------------------------------------------
extern "C" void kernel_launch(void* const* d_in, const int* in_sizes, int n_in,
                              void* d_out, int out_size) {
    const int4* x = (const int4*)d_in[0];
    float4* out = (float4*)d_out;

    dim3 grid(BPR, BATCH);
    fused_kernel<<<grid, HTHREADS>>>(x, out);
}

// round 8
// speedup vs baseline: 1.2650x; 1.1661x over previous
#include <cuda_runtime.h>
#include <cstdint>

// Problem constants
#define BATCH     64
#define NPER      786432
#define VPER      (NPER / 4)              // 196608 int4 per row
#define LEVELS    256
#define HTHREADS  256
#define BPR       8                       // CTAs per row -> 512 CTAs (round-5 optimum)
#define V_PER_CTA (VPER / BPR)            // 24576 int4
#define ITERS     (V_PER_CTA / HTHREADS)  // 96 int4 per thread

// Statically zero; each launch restores zeros -> graph-replay deterministic.
__device__ unsigned int g_hist[BATCH * LEVELS];
__device__ unsigned int g_cnt[BATCH];     // arrival tickets
__device__ unsigned int g_flag[BATCH];    // row-complete flag
__device__ unsigned int g_done[BATCH];    // broadcast-done tickets

// NOTE: no "memory" clobber -> the compiler may batch subsequent LDGs above
// these (wanted: MLP). volatile keeps program order among the REDs themselves
// and vs __syncthreads. RED touches only smem counters; input is const global.
#define REDS(addr) asm volatile("red.shared.add.u32 [%0], %1;" \
                                :: "r"(addr), "r"(1u))

__global__ void __launch_bounds__(HTHREADS, 4)
fused_kernel(const int4* __restrict__ x, float4* __restrict__ out) {
    __shared__ unsigned int sh[LEVELS * 32];   // 32 KB
    __shared__ unsigned int s_dummy;           // (keeps layout parity)

    #pragma unroll
    for (int i = threadIdx.x; i < LEVELS * 32; i += HTHREADS) sh[i] = 0u;
    __syncthreads();

    const unsigned lane = threadIdx.x & 31u;
    unsigned int hbase = (unsigned int)__cvta_generic_to_shared(sh) + (lane << 2);

    const int b = blockIdx.y;
    const int i = blockIdx.x;
    const int4* __restrict__ blk =
        x + (size_t)b * VPER + (size_t)i * V_PER_CTA;

    // 4 batched LDG.128 per body (MLP_p1 = 4), then 16 REDs.
    for (int it = 0; it < ITERS; it += 4) {
        int4 v0 = blk[(it + 0) * HTHREADS + threadIdx.x];
        int4 v1 = blk[(it + 1) * HTHREADS + threadIdx.x];
        int4 v2 = blk[(it + 2) * HTHREADS + threadIdx.x];
        int4 v3 = blk[(it + 3) * HTHREADS + threadIdx.x];

        REDS(hbase + ((unsigned)v0.x << 7));
        REDS(hbase + ((unsigned)v0.y << 7));
        REDS(hbase + ((unsigned)v0.z << 7));
        REDS(hbase + ((unsigned)v0.w << 7));
        REDS(hbase + ((unsigned)v1.x << 7));
        REDS(hbase + ((unsigned)v1.y << 7));
        REDS(hbase + ((unsigned)v1.z << 7));
        REDS(hbase + ((unsigned)v1.w << 7));
        REDS(hbase + ((unsigned)v2.x << 7));
        REDS(hbase + ((unsigned)v2.y << 7));
        REDS(hbase + ((unsigned)v2.z << 7));
        REDS(hbase + ((unsigned)v2.w << 7));
        REDS(hbase + ((unsigned)v3.x << 7));
        REDS(hbase + ((unsigned)v3.y << 7));
        REDS(hbase + ((unsigned)v3.z << 7));
        REDS(hbase + ((unsigned)v3.w << 7));
    }
    __syncthreads();   // BAR.SYNC drains pending smem ops (HW-native)

    // Reduce the 32 lane-copies of bin t (rotated -> conflict-free), one REDG.
    {
        const unsigned t = threadIdx.x;
        unsigned int s = 0;
        #pragma unroll
        for (int c = 0; c < 32; c++) s += sh[t * 32 + ((c + t) & 31u)];
        atomicAdd(&g_hist[(unsigned)b * LEVELS + t], s);
    }

    // ---- Row-completion spin-release (512 CTAs <= 4/SM*148 -> one wave) ----
    __threadfence();
    __syncthreads();
    if (threadIdx.x == 0) {
        unsigned t = atomicAdd(&g_cnt[b], 1u);
        if (t == BPR - 1) atomicExch(&g_flag[b], 1u);
        while (*(volatile unsigned*)&g_flag[b] == 0u) __nanosleep(64);
    }
    __syncthreads();
    __threadfence();   // acquire: row-b g_hist complete

    // ---- Broadcast bins [i*32, i*32+32) of row b ----
    float* shf = (float*)sh;
    const unsigned binBase = (unsigned)b * LEVELS + (unsigned)i * 32u;
    if (threadIdx.x < 32) {
        shf[threadIdx.x] = (float)g_hist[binBase + threadIdx.x];
        g_hist[binBase + threadIdx.x] = 0u;   // disjoint slice -> safe reset
    }
    __syncthreads();

    float4* __restrict__ dst =
        out + ((size_t)b * LEVELS + (size_t)i * 32u) * (LEVELS / 4);
    #pragma unroll
    for (int k = threadIdx.x; k < 32 * (LEVELS / 4); k += HTHREADS) {
        float v = shf[k >> 6];
        dst[k] = make_float4(v, v, v, v);
    }

    // last CTA of the row to finish resets the sync words
    if (threadIdx.x == 0) {
        __threadfence();
        unsigned d = atomicAdd(&g_done[b], 1u);
        if (d == BPR - 1) {
            g_cnt[b]  = 0u;
            g_flag[b] = 0u;
            g_done[b] = 0u;
            __threadfence();
        }
    }
}

// ---------------------------------------------------------------------------
extern "C" void kernel_launch(void* const* d_in, const int* in_sizes, int n_in,
                              void* d_out, int out_size) {
    const int4* x = (const int4*)d_in[0];
    float4* out = (float4*)d_out;

    dim3 grid(BPR, BATCH);
    fused_kernel<<<grid, HTHREADS>>>(x, out);
}